// round 3
// baseline (speedup 1.0000x reference)
#include <cuda_runtime.h>
#include <cstdint>

#define Bn 32
#define Hn 56
#define Wn 56
#define Cn 256
#define RS (Wn * Cn)

typedef unsigned long long ull;
typedef unsigned int u32;

// ---- packed f32x2 helpers (Blackwell FFMA2 path: only reachable via PTX) ----
__device__ __forceinline__ ull fma2(ull a, ull b, ull c) {
    ull d; asm("fma.rn.f32x2 %0, %1, %2, %3;" : "=l"(d) : "l"(a), "l"(b), "l"(c)); return d;
}
__device__ __forceinline__ ull mul2(ull a, ull b) {
    ull d; asm("mul.rn.f32x2 %0, %1, %2;" : "=l"(d) : "l"(a), "l"(b)); return d;
}
__device__ __forceinline__ ull add2(ull a, ull b) {
    ull d; asm("add.rn.f32x2 %0, %1, %2;" : "=l"(d) : "l"(a), "l"(b)); return d;
}
__device__ __forceinline__ ull pk2(u32 lo, u32 hi) {
    ull d; asm("mov.b64 %0, {%1, %2};" : "=l"(d) : "r"(lo), "r"(hi)); return d;
}
__device__ __forceinline__ ull dup2(u32 v) {
    ull d; asm("mov.b64 %0, {%1, %1};" : "=l"(d) : "r"(v)); return d;
}
__device__ __forceinline__ void up2(ull v, u32 &lo, u32 &hi) {
    asm("mov.b64 {%0, %1}, %2;" : "=r"(lo), "=r"(hi) : "l"(v));
}

__global__ void __launch_bounds__(256, 3) gdn_kernel(
    const float* __restrict__ x,  const float* __restrict__ gk,
    const float* __restrict__ gs, const float* __restrict__ beta,
    const float* __restrict__ bo, const float* __restrict__ go,
    float* __restrict__ out)
{
    const int tid = threadIdx.x;
    const int ct  = tid & 127;     // channel-thread: channels [2ct, 2ct+2)
    const int col = tid >> 7;      // 0..1 : w column within block
    const int cb  = ct * 2;
    const int qid = ct & 3;        // position within 4-thread group quad

    int bi = blockIdx.x;
    const int wq = bi % 28; bi /= 28;
    const int hq = bi & 3;  bi >>= 2;
    const int b  = bi;
    const int w  = wq * 2 + col;
    const int h0 = hq * 14;
    const bool wl = (w > 0), wr = (w < Wn - 1);

    // ---- Pk weights, pre-permuted into shuffle-delivery order ----
    // shuffles deliver the group inputs held by threads qid^0, qid^1, qid^2, qid^3
    ull Wp[8];
#pragma unroll
    for (int j = 0; j < 4; j++) {
        const int src = qid ^ j;
        Wp[2 * j]     = *(const ull*)(gk + (2 * src)     * Cn + cb);
        Wp[2 * j + 1] = *(const ull*)(gk + (2 * src + 1) * Cn + cb);
    }
    // ---- Ps taps (3x3 minus center) ----
    const int tapi[8] = {0, 1, 2, 3, 5, 6, 7, 8};
    ull kp[8];
#pragma unroll
    for (int t = 0; t < 8; t++)
        kp[t] = *(const ull*)(gs + tapi[t] * Cn + cb);

    float2 bt = *(const float2*)(beta + cb);
    const ull bp  = pk2(__float_as_uint(bt.x + 1e-6f), __float_as_uint(bt.y + 1e-6f));
    const ull gov = *(const ull*)(go + cb);
    const ull bov = *(const ull*)(bo + cb);

    const float* xw = x   + (((size_t)b * Hn) * Wn + w) * Cn + cb;
    float*       ob = out + (((size_t)b * Hn) * Wn + w) * Cn + cb;

    auto ldrow = [&](int hg, ull &L, ull &C, ull &R) {
        L = 0; C = 0; R = 0;
        if (hg >= 0 && hg < Hn) {
            const float* p = xw + (size_t)hg * RS;
            if (wl) L = *(const ull*)(p - Cn);
            C = *(const ull*)(p);
            if (wr) R = *(const ull*)(p + Cn);
        }
    };

    // squared window rows h-1, h, h+1  (cols w-1, w, w+1)
    ull w00, w01, w02, w10, w11, w12, w20, w21, w22;
    ull rawc, rawn;          // raw center x for rows h, h+1
    ull fl, fc, fr;          // in-flight raw loads for row h+2

    {
        ull L, C, R;
        ldrow(h0 - 1, L, C, R);
        w00 = mul2(L, L); w01 = mul2(C, C); w02 = mul2(R, R);
        ldrow(h0, L, C, R);
        w10 = mul2(L, L); w11 = mul2(C, C); w12 = mul2(R, R);
        rawc = C;
        ldrow(h0 + 1, L, C, R);
        w20 = mul2(L, L); w21 = mul2(C, C); w22 = mul2(R, R);
        rawn = C;
        ldrow(h0 + 2, fl, fc, fr);   // prefetch
    }

#pragma unroll
    for (int s = 0; s < 14; s++) {
        const int h = h0 + s;

        // ---- Pk inputs: three INDEPENDENT butterflies off the center value ----
        const ull va = w11;
        const ull vb = __shfl_xor_sync(0xffffffffu, va, 1);
        const ull vc = __shfl_xor_sync(0xffffffffu, va, 2);
        const ull vd = __shfl_xor_sync(0xffffffffu, va, 3);

        // ---- 4 independent accumulator chains ----
        ull accA = bp;              // beta + BETA_MIN
        ull accB;
        u32 s0, s1;
        up2(va, s0, s1);
        accA = fma2(dup2(s0), Wp[0], accA);
        accB = mul2(dup2(s1), Wp[1]);
        up2(vb, s0, s1);
        accA = fma2(dup2(s0), Wp[2], accA);
        accB = fma2(dup2(s1), Wp[3], accB);
        up2(vc, s0, s1);
        accA = fma2(dup2(s0), Wp[4], accA);
        accB = fma2(dup2(s1), Wp[5], accB);
        up2(vd, s0, s1);
        accA = fma2(dup2(s0), Wp[6], accA);
        accB = fma2(dup2(s1), Wp[7], accB);

        // Ps: masked 3x3 surround on x^2 (2 more chains)
        ull accC = mul2(w00, kp[0]);
        ull accD = mul2(w01, kp[1]);
        accC = fma2(w02, kp[2], accC);
        accD = fma2(w10, kp[3], accD);
        accC = fma2(w12, kp[4], accC);
        accD = fma2(w20, kp[5], accD);
        accC = fma2(w21, kp[6], accC);
        accD = fma2(w22, kp[7], accD);

        const ull acc = add2(add2(accA, accB), add2(accC, accD));

        // ---- epilogue: x * rsqrt(acc) * gamma_o + beta_o ----
        u32 a0, a1;
        up2(acc, a0, a1);
        const float r0 = rsqrtf(__uint_as_float(a0));
        const float r1 = rsqrtf(__uint_as_float(a1));
        const ull rp = pk2(__float_as_uint(r0), __float_as_uint(r1));
        *(ull*)(ob + (size_t)h * RS) = fma2(mul2(rawc, rp), gov, bov);

        // ---- shift window; absorb in-flight loads; issue next prefetch ----
        w00 = w10; w01 = w11; w02 = w12;
        w10 = w20; w11 = w21; w12 = w22;
        rawc = rawn;
        w20 = mul2(fl, fl); w21 = mul2(fc, fc); w22 = mul2(fr, fr);
        rawn = fc;
        ldrow(h + 3, fl, fc, fr);
    }
}

extern "C" void kernel_launch(void* const* d_in, const int* in_sizes, int n_in,
                              void* d_out, int out_size) {
    const float* x    = (const float*)d_in[0];
    const float* gk   = (const float*)d_in[1];
    const float* gs   = (const float*)d_in[2];
    const float* beta = (const float*)d_in[3];
    const float* bo   = (const float*)d_in[4];
    const float* go   = (const float*)d_in[5];
    gdn_kernel<<<Bn * 4 * 28, 256>>>(x, gk, gs, beta, bo, go, (float*)d_out);
}

// round 4
// speedup vs baseline: 1.2283x; 1.2283x over previous
#include <cuda_runtime.h>
#include <cstdint>

#define Bn 32
#define Hn 56
#define Wn 56
#define Cn 256
#define RS (Wn * Cn)

typedef unsigned long long ull;
typedef unsigned int u32;

// ---- packed f32x2 helpers (Blackwell FFMA2 path: only reachable via PTX) ----
__device__ __forceinline__ ull fma2(ull a, ull b, ull c) {
    ull d; asm("fma.rn.f32x2 %0, %1, %2, %3;" : "=l"(d) : "l"(a), "l"(b), "l"(c)); return d;
}
__device__ __forceinline__ ull mul2(ull a, ull b) {
    ull d; asm("mul.rn.f32x2 %0, %1, %2;" : "=l"(d) : "l"(a), "l"(b)); return d;
}
__device__ __forceinline__ ull add2(ull a, ull b) {
    ull d; asm("add.rn.f32x2 %0, %1, %2;" : "=l"(d) : "l"(a), "l"(b)); return d;
}
__device__ __forceinline__ ull pk2(u32 lo, u32 hi) {
    ull d; asm("mov.b64 %0, {%1, %2};" : "=l"(d) : "r"(lo), "r"(hi)); return d;
}
__device__ __forceinline__ ull dup2(u32 v) {
    ull d; asm("mov.b64 %0, {%1, %1};" : "=l"(d) : "r"(v)); return d;
}
__device__ __forceinline__ void up2(ull v, u32 &lo, u32 &hi) {
    asm("mov.b64 {%0, %1}, %2;" : "=r"(lo), "=r"(hi) : "l"(v));
}

__global__ void __launch_bounds__(256, 3) gdn_kernel(
    const float* __restrict__ x,  const float* __restrict__ gk,
    const float* __restrict__ gs, const float* __restrict__ beta,
    const float* __restrict__ bo, const float* __restrict__ go,
    float* __restrict__ out)
{
    const int tid = threadIdx.x;
    const int ct  = tid & 127;     // channel-thread: channels [2ct, 2ct+2)
    const int col = tid >> 7;      // 0..1 : w column within block
    const int cb  = ct * 2;
    const int qid = ct & 3;        // position within 4-thread group quad

    int bi = blockIdx.x;
    const int wq = bi % 28; bi /= 28;
    const int hq = bi & 3;  bi >>= 2;
    const int b  = bi;
    const int w  = wq * 2 + col;
    const int h0 = hq * 14;
    const bool wl = (w > 0), wr = (w < Wn - 1);

    // ---- Pk weights, pre-permuted into shuffle-delivery order ----
    ull Wp[8];
#pragma unroll
    for (int j = 0; j < 4; j++) {
        const int src = qid ^ j;
        Wp[2 * j]     = *(const ull*)(gk + (2 * src)     * Cn + cb);
        Wp[2 * j + 1] = *(const ull*)(gk + (2 * src + 1) * Cn + cb);
    }
    // ---- Ps taps (3x3 minus center): (0,0)(0,1)(0,2)(1,0)(1,2)(2,0)(2,1)(2,2)
    const int tapi[8] = {0, 1, 2, 3, 5, 6, 7, 8};
    ull kp[8];
#pragma unroll
    for (int t = 0; t < 8; t++)
        kp[t] = *(const ull*)(gs + tapi[t] * Cn + cb);

    float2 bt = *(const float2*)(beta + cb);
    const ull bp  = pk2(__float_as_uint(bt.x + 1e-6f), __float_as_uint(bt.y + 1e-6f));
    const ull gov = *(const ull*)(go + cb);
    const ull bov = *(const ull*)(bo + cb);

    const float* xw = x   + (((size_t)b * Hn) * Wn + w) * Cn + cb;
    float*       ob = out + (((size_t)b * Hn) * Wn + w) * Cn + cb;

    auto ldrow = [&](int hg, ull &L, ull &C, ull &R) {
        L = 0; C = 0; R = 0;
        if (hg >= 0 && hg < Hn) {
            const float* p = xw + (size_t)hg * RS;
            if (wl) L = *(const ull*)(p - Cn);
            C = *(const ull*)(p);
            if (wr) R = *(const ull*)(p + Cn);
        }
    };

    // window rows a(h-1), b(h), c(h+1): L/R columns SQUARED, center RAW
    ull aL, aC, aR, bL, bC, bR, cL, cC, cR;
    // raw prefetch rows h+2 and h+3 (depth-2 pipeline)
    ull p1L, p1C, p1R, p2L, p2C, p2R;

    {
        ull L, C, R;
        ldrow(h0 - 1, L, C, R); aL = mul2(L, L); aC = C; aR = mul2(R, R);
        ldrow(h0,     L, C, R); bL = mul2(L, L); bC = C; bR = mul2(R, R);
        ldrow(h0 + 1, L, C, R); cL = mul2(L, L); cC = C; cR = mul2(R, R);
        ldrow(h0 + 2, p1L, p1C, p1R);
        ldrow(h0 + 3, p2L, p2C, p2R);
    }

#pragma unroll
    for (int s = 0; s < 14; s++) {
        const int h = h0 + s;

        // center column squares (raw kept for output)
        const ull sqA = mul2(aC, aC);
        const ull sqB = mul2(bC, bC);
        const ull sqC = mul2(cC, cC);

        // ---- Pk inputs: three independent butterflies off the center x^2 ----
        const ull vb = __shfl_xor_sync(0xffffffffu, sqB, 1);
        const ull vc = __shfl_xor_sync(0xffffffffu, sqB, 2);
        const ull vd = __shfl_xor_sync(0xffffffffu, sqB, 3);

        ull accA = bp, accB;            // beta + BETA_MIN
        u32 s0, s1;
        up2(sqB, s0, s1);
        accA = fma2(dup2(s0), Wp[0], accA);
        accB = mul2(dup2(s1), Wp[1]);
        up2(vb, s0, s1);
        accA = fma2(dup2(s0), Wp[2], accA);
        accB = fma2(dup2(s1), Wp[3], accB);
        up2(vc, s0, s1);
        accA = fma2(dup2(s0), Wp[4], accA);
        accB = fma2(dup2(s1), Wp[5], accB);
        up2(vd, s0, s1);
        accA = fma2(dup2(s0), Wp[6], accA);
        accB = fma2(dup2(s1), Wp[7], accB);

        // ---- Ps: masked 3x3 surround on x^2 ----
        ull accC = mul2(aL, kp[0]);
        ull accD = mul2(sqA, kp[1]);
        accC = fma2(aR, kp[2], accC);
        accD = fma2(bL, kp[3], accD);
        accC = fma2(bR, kp[4], accC);
        accD = fma2(cL, kp[5], accD);
        accC = fma2(sqC, kp[6], accC);
        accD = fma2(cR, kp[7], accD);

        const ull acc = add2(add2(accA, accB), add2(accC, accD));

        // ---- epilogue: x * rsqrt(acc) * gamma_o + beta_o ----
        u32 a0, a1;
        up2(acc, a0, a1);
        const float r0 = rsqrtf(__uint_as_float(a0));
        const float r1 = rsqrtf(__uint_as_float(a1));
        const ull rp = pk2(__float_as_uint(r0), __float_as_uint(r1));
        *(ull*)(ob + (size_t)h * RS) = fma2(mul2(bC, rp), gov, bov);

        // ---- shift window; absorb prefetch row 1; rotate; issue new load ----
        aL = bL; aC = bC; aR = bR;
        bL = cL; bC = cC; bR = cR;
        cL = mul2(p1L, p1L); cC = p1C; cR = mul2(p1R, p1R);
        p1L = p2L; p1C = p2C; p1R = p2R;
        ldrow(h + 4, p2L, p2C, p2R);
    }
}

extern "C" void kernel_launch(void* const* d_in, const int* in_sizes, int n_in,
                              void* d_out, int out_size) {
    const float* x    = (const float*)d_in[0];
    const float* gk   = (const float*)d_in[1];
    const float* gs   = (const float*)d_in[2];
    const float* beta = (const float*)d_in[3];
    const float* bo   = (const float*)d_in[4];
    const float* go   = (const float*)d_in[5];
    gdn_kernel<<<Bn * 4 * 28, 256>>>(x, gk, gs, beta, bo, go, (float*)d_out);
}

// round 5
// speedup vs baseline: 1.4755x; 1.2013x over previous
#include <cuda_runtime.h>
#include <cstdint>

#define Bn 32
#define Hn 56
#define Wn 56
#define Cn 256
#define RS (Wn * Cn)

typedef unsigned long long ull;
typedef unsigned int u32;

// ---- packed f32x2 helpers (Blackwell FFMA2 path: only reachable via PTX) ----
__device__ __forceinline__ ull fma2(ull a, ull b, ull c) {
    ull d; asm("fma.rn.f32x2 %0, %1, %2, %3;" : "=l"(d) : "l"(a), "l"(b), "l"(c)); return d;
}
__device__ __forceinline__ ull mul2(ull a, ull b) {
    ull d; asm("mul.rn.f32x2 %0, %1, %2;" : "=l"(d) : "l"(a), "l"(b)); return d;
}
__device__ __forceinline__ ull add2(ull a, ull b) {
    ull d; asm("add.rn.f32x2 %0, %1, %2;" : "=l"(d) : "l"(a), "l"(b)); return d;
}
__device__ __forceinline__ ull pk2(u32 lo, u32 hi) {
    ull d; asm("mov.b64 %0, {%1, %2};" : "=l"(d) : "r"(lo), "r"(hi)); return d;
}
__device__ __forceinline__ ull dup2(u32 v) {
    ull d; asm("mov.b64 %0, {%1, %1};" : "=l"(d) : "r"(v)); return d;
}
__device__ __forceinline__ void up2(ull v, u32 &lo, u32 &hi) {
    asm("mov.b64 {%0, %1}, %2;" : "=r"(lo), "=r"(hi) : "l"(v));
}

__global__ void __launch_bounds__(128, 5) gdn_kernel(
    const float* __restrict__ x,  const float* __restrict__ gk,
    const float* __restrict__ gs, const float* __restrict__ beta,
    const float* __restrict__ bo, const float* __restrict__ go,
    float* __restrict__ out)
{
    const int ct  = threadIdx.x;     // channel-thread: channels [2ct, 2ct+2)
    const int cb  = ct * 2;
    const int qid = ct & 3;          // position within 4-thread group quad

    int bi = blockIdx.x;
    const int wp = bi % 28; bi /= 28;   // w-pair: output cols w0, w0+1
    const int hq = bi & 3;  bi >>= 2;
    const int b  = bi;
    const int w0 = wp * 2;
    const int h0 = hq * 14;
    const bool wl = (wp > 0), wr = (wp < 27);

    // ---- Pk weights, pre-permuted into shuffle-delivery order ----
    ull Wp[8];
#pragma unroll
    for (int j = 0; j < 4; j++) {
        const int src = qid ^ j;
        Wp[2 * j]     = *(const ull*)(gk + (2 * src)     * Cn + cb);
        Wp[2 * j + 1] = *(const ull*)(gk + (2 * src + 1) * Cn + cb);
    }
    // ---- Ps taps (3x3 minus center) ----
    const int tapi[8] = {0, 1, 2, 3, 5, 6, 7, 8};
    ull kp[8];
#pragma unroll
    for (int t = 0; t < 8; t++)
        kp[t] = *(const ull*)(gs + tapi[t] * Cn + cb);

    float2 bt = *(const float2*)(beta + cb);
    const ull bp  = pk2(__float_as_uint(bt.x + 1e-6f), __float_as_uint(bt.y + 1e-6f));
    const ull gov = *(const ull*)(go + cb);
    const ull bov = *(const ull*)(bo + cb);

    const float* xw = x   + (((size_t)b * Hn) * Wn + w0) * Cn + cb;
    float*       ob = out + (((size_t)b * Hn) * Wn + w0) * Cn + cb;

    // load 4 raw columns (w0-1, w0, w0+1, w0+2) of row hg
    auto ldrow = [&](int hg, ull &L, ull &C0, ull &C1, ull &R) {
        L = 0; C0 = 0; C1 = 0; R = 0;
        if (hg >= 0 && hg < Hn) {
            const float* p = xw + (size_t)hg * RS;
            if (wl) L = *(const ull*)(p - Cn);
            C0 = *(const ull*)(p);
            C1 = *(const ull*)(p + Cn);
            if (wr) R = *(const ull*)(p + 2 * Cn);
        }
    };

    // squared window rows a(h-1), b(h), c(h+1) x cols (w0-1, w0, w0+1, w0+2)
    ull aSL, aS0, aS1, aSR, bSL, bS0, bS1, bSR, cSL, cS0, cS1, cSR;
    ull rb0, rb1, rc0, rc1;          // raw center cols for rows h (out) and h+1
    ull p1L, p1C0, p1C1, p1R;        // raw prefetch row h+2
    ull p2L, p2C0, p2C1, p2R;        // raw prefetch row h+3

    {
        ull L, C0, C1, R;
        ldrow(h0 - 1, L, C0, C1, R);
        aSL = mul2(L, L); aS0 = mul2(C0, C0); aS1 = mul2(C1, C1); aSR = mul2(R, R);
        ldrow(h0, L, C0, C1, R);
        bSL = mul2(L, L); bS0 = mul2(C0, C0); bS1 = mul2(C1, C1); bSR = mul2(R, R);
        rb0 = C0; rb1 = C1;
        ldrow(h0 + 1, L, C0, C1, R);
        cSL = mul2(L, L); cS0 = mul2(C0, C0); cS1 = mul2(C1, C1); cSR = mul2(R, R);
        rc0 = C0; rc1 = C1;
        ldrow(h0 + 2, p1L, p1C0, p1C1, p1R);
        ldrow(h0 + 3, p2L, p2C0, p2C1, p2R);
    }

#pragma unroll
    for (int s = 0; s < 14; s++) {
        const int h = h0 + s;

        // ---- Pk inputs: independent butterflies off both center x^2 cols ----
        const ull v0b = __shfl_xor_sync(0xffffffffu, bS0, 1);
        const ull v0c = __shfl_xor_sync(0xffffffffu, bS0, 2);
        const ull v0d = __shfl_xor_sync(0xffffffffu, bS0, 3);
        const ull v1b = __shfl_xor_sync(0xffffffffu, bS1, 1);
        const ull v1c = __shfl_xor_sync(0xffffffffu, bS1, 2);
        const ull v1d = __shfl_xor_sync(0xffffffffu, bS1, 3);

        u32 s0, s1;
        // ---- col w0: Pk (2 chains) ----
        ull A0 = bp, B0;
        up2(bS0, s0, s1);
        A0 = fma2(dup2(s0), Wp[0], A0);  B0 = mul2(dup2(s1), Wp[1]);
        up2(v0b, s0, s1);
        A0 = fma2(dup2(s0), Wp[2], A0);  B0 = fma2(dup2(s1), Wp[3], B0);
        up2(v0c, s0, s1);
        A0 = fma2(dup2(s0), Wp[4], A0);  B0 = fma2(dup2(s1), Wp[5], B0);
        up2(v0d, s0, s1);
        A0 = fma2(dup2(s0), Wp[6], A0);  B0 = fma2(dup2(s1), Wp[7], B0);
        // ---- col w0: Ps (2 chains) ----
        ull C0a = mul2(aSL, kp[0]);
        ull D0a = mul2(aS0, kp[1]);
        C0a = fma2(aS1, kp[2], C0a);
        D0a = fma2(bSL, kp[3], D0a);
        C0a = fma2(bS1, kp[4], C0a);
        D0a = fma2(cSL, kp[5], D0a);
        C0a = fma2(cS0, kp[6], C0a);
        D0a = fma2(cS1, kp[7], D0a);
        const ull acc0 = add2(add2(A0, B0), add2(C0a, D0a));

        // ---- col w0+1: Pk ----
        ull A1 = bp, B1;
        up2(bS1, s0, s1);
        A1 = fma2(dup2(s0), Wp[0], A1);  B1 = mul2(dup2(s1), Wp[1]);
        up2(v1b, s0, s1);
        A1 = fma2(dup2(s0), Wp[2], A1);  B1 = fma2(dup2(s1), Wp[3], B1);
        up2(v1c, s0, s1);
        A1 = fma2(dup2(s0), Wp[4], A1);  B1 = fma2(dup2(s1), Wp[5], B1);
        up2(v1d, s0, s1);
        A1 = fma2(dup2(s0), Wp[6], A1);  B1 = fma2(dup2(s1), Wp[7], B1);
        // ---- col w0+1: Ps ----
        ull C1a = mul2(aS0, kp[0]);
        ull D1a = mul2(aS1, kp[1]);
        C1a = fma2(aSR, kp[2], C1a);
        D1a = fma2(bS0, kp[3], D1a);
        C1a = fma2(bSR, kp[4], C1a);
        D1a = fma2(cS0, kp[5], D1a);
        C1a = fma2(cS1, kp[6], C1a);
        D1a = fma2(cSR, kp[7], D1a);
        const ull acc1 = add2(add2(A1, B1), add2(C1a, D1a));

        // ---- epilogue: x * rsqrt(acc) * gamma_o + beta_o (both cols) ----
        u32 a0, a1;
        float* po = ob + (size_t)h * RS;
        up2(acc0, a0, a1);
        {
            const float r0 = rsqrtf(__uint_as_float(a0));
            const float r1 = rsqrtf(__uint_as_float(a1));
            const ull rp = pk2(__float_as_uint(r0), __float_as_uint(r1));
            *(ull*)(po) = fma2(mul2(rb0, rp), gov, bov);
        }
        up2(acc1, a0, a1);
        {
            const float r0 = rsqrtf(__uint_as_float(a0));
            const float r1 = rsqrtf(__uint_as_float(a1));
            const ull rp = pk2(__float_as_uint(r0), __float_as_uint(r1));
            *(ull*)(po + Cn) = fma2(mul2(rb1, rp), gov, bov);
        }

        // ---- shift window; absorb prefetch row 1; rotate; issue new load ----
        aSL = bSL; aS0 = bS0; aS1 = bS1; aSR = bSR;
        bSL = cSL; bS0 = cS0; bS1 = cS1; bSR = cSR;
        cSL = mul2(p1L, p1L);  cS0 = mul2(p1C0, p1C0);
        cS1 = mul2(p1C1, p1C1); cSR = mul2(p1R, p1R);
        rb0 = rc0; rb1 = rc1;
        rc0 = p1C0; rc1 = p1C1;
        p1L = p2L; p1C0 = p2C0; p1C1 = p2C1; p1R = p2R;
        ldrow(h + 4, p2L, p2C0, p2C1, p2R);
    }
}

extern "C" void kernel_launch(void* const* d_in, const int* in_sizes, int n_in,
                              void* d_out, int out_size) {
    const float* x    = (const float*)d_in[0];
    const float* gk   = (const float*)d_in[1];
    const float* gs   = (const float*)d_in[2];
    const float* beta = (const float*)d_in[3];
    const float* bo   = (const float*)d_in[4];
    const float* go   = (const float*)d_in[5];
    gdn_kernel<<<Bn * 4 * 28, 128>>>(x, gk, gs, beta, bo, go, (float*)d_out);
}